// round 7
// baseline (speedup 1.0000x reference)
#include <cuda_runtime.h>
#include <cuda_fp16.h>

#define NX 256
#define NY 256
#define NZ 256
#define DETU 128
#define DETV 128
#define NVIEWS 8
#define NSTEPS 192

// Packed volume: g_pair[((x*NY+y)*NZ+z)] = ( half(v[x][y][z]), half(v[x][y][z+1]) )
__device__ __half2 g_pair[NX * NY * NZ];   // 64 MB

// ---------------------------------------------------------------------------
// Kernel A (fused): relu_out = max(x+reco, 0) ; g_pair = half2 z-pairs of x+reco
// ---------------------------------------------------------------------------
__global__ void add_relu_pack_kernel(const float* __restrict__ x,
                                     const float* __restrict__ r,
                                     float* __restrict__ relu_out) {
    int i = blockIdx.x * blockDim.x + threadIdx.x;   // float4 index
    const float4* x4 = (const float4*)x;
    const float4* r4 = (const float4*)r;
    float4 a = x4[i];
    float4 b = r4[i];
    float4 s;
    s.x = a.x + b.x; s.y = a.y + b.y; s.z = a.z + b.z; s.w = a.w + b.w;

    float4 rl;
    rl.x = fmaxf(s.x, 0.0f); rl.y = fmaxf(s.y, 0.0f);
    rl.z = fmaxf(s.z, 0.0f); rl.w = fmaxf(s.w, 0.0f);
    ((float4*)relu_out)[i] = rl;

    int base = i * 4;
    int z = base & (NZ - 1);
    float s4 = 0.0f;
    if (z + 4 < NZ) s4 = x[base + 4] + r[base + 4];

    union { __half2 h[4]; uint4 u; } pk;
    pk.h[0] = __floats2half2_rn(s.x, s.y);
    pk.h[1] = __floats2half2_rn(s.y, s.z);
    pk.h[2] = __floats2half2_rn(s.z, s.w);
    pk.h[3] = __floats2half2_rn(s.w, s4);
    ((uint4*)g_pair)[i] = pk.u;
}

// ---------------------------------------------------------------------------
// Voxel accessor for the masked (boundary) path: v[idx] = g_pair[idx].x
// ---------------------------------------------------------------------------
__device__ __forceinline__ float vol_at(int idx) {
    return __half2float(((const __half*)g_pair)[idx * 2]);
}

// Masked trilinear sample (boundary steps only): zero-outside semantics
__device__ __forceinline__ float trilin_masked(float px, float py, float pz) {
    float xf = floorf(px), yf = floorf(py), zf = floorf(pz);
    float fx = px - xf, fy = py - yf, fz = pz - zf;
    int x0 = (int)xf, y0 = (int)yf, z0 = (int)zf;
    int x1 = x0 + 1, y1 = y0 + 1, z1 = z0 + 1;

    bool bx0 = ((unsigned)x0 < (unsigned)NX);
    bool bx1 = ((unsigned)x1 < (unsigned)NX);
    bool by0 = ((unsigned)y0 < (unsigned)NY);
    bool by1 = ((unsigned)y1 < (unsigned)NY);
    bool bz0 = ((unsigned)z0 < (unsigned)NZ);
    bool bz1 = ((unsigned)z1 < (unsigned)NZ);

    int cx0 = min(max(x0, 0), NX - 1), cx1 = min(max(x1, 0), NX - 1);
    int cy0 = min(max(y0, 0), NY - 1), cy1 = min(max(y1, 0), NY - 1);
    int cz0 = min(max(z0, 0), NZ - 1), cz1 = min(max(z1, 0), NZ - 1);

    int bx0i = cx0 * (NY * NZ), bx1i = cx1 * (NY * NZ);
    int oy0 = cy0 * NZ, oy1 = cy1 * NZ;

    float v000 = (bx0 & by0 & bz0) ? vol_at(bx0i + oy0 + cz0) : 0.0f;
    float v001 = (bx0 & by0 & bz1) ? vol_at(bx0i + oy0 + cz1) : 0.0f;
    float v010 = (bx0 & by1 & bz0) ? vol_at(bx0i + oy1 + cz0) : 0.0f;
    float v011 = (bx0 & by1 & bz1) ? vol_at(bx0i + oy1 + cz1) : 0.0f;
    float v100 = (bx1 & by0 & bz0) ? vol_at(bx1i + oy0 + cz0) : 0.0f;
    float v101 = (bx1 & by0 & bz1) ? vol_at(bx1i + oy0 + cz1) : 0.0f;
    float v110 = (bx1 & by1 & bz0) ? vol_at(bx1i + oy1 + cz0) : 0.0f;
    float v111 = (bx1 & by1 & bz1) ? vol_at(bx1i + oy1 + cz1) : 0.0f;

    float gz = 1.0f - fz, gy = 1.0f - fy, gx = 1.0f - fx;
    float c00 = v000 * gz + v001 * fz;
    float c01 = v010 * gz + v011 * fz;
    float c10 = v100 * gz + v101 * fz;
    float c11 = v110 * gz + v111 * fz;
    float c0 = c00 * gy + c01 * fy;
    float c1 = c10 * gy + c11 * fy;
    return c0 * gx + c1 * fx;
}

// combine 4 packed corner loads with weights
__device__ __forceinline__ float tri_combine(__half2 A, __half2 B, __half2 C, __half2 D,
                                             float fx, float fy, float fz) {
    float2 a = __half22float2(A);
    float2 b = __half22float2(B);
    float2 c = __half22float2(C);
    float2 d = __half22float2(D);
    float gz = 1.0f - fz, gy = 1.0f - fy, gx = 1.0f - fx;
    float c00 = a.x * gz + a.y * fz;
    float c01 = b.x * gz + b.y * fz;
    float c10 = c.x * gz + c.y * fz;
    float c11 = d.x * gz + d.y * fz;
    float c0 = c00 * gy + c01 * fy;
    float c1 = c10 * gy + c11 * fy;
    return c0 * gx + c1 * fx;
}

// Single fast interior sample (tail)
__device__ __forceinline__ float trilin_fast(float px, float py, float pz) {
    float xf = floorf(px), yf = floorf(py), zf = floorf(pz);
    float fx = px - xf, fy = py - yf, fz = pz - zf;
    int x0 = (int)xf, y0 = (int)yf, z0 = (int)zf;
    const __half2* p = g_pair + ((x0 * NY + y0) * NZ + z0);
    return tri_combine(__ldg(p), __ldg(p + NZ), __ldg(p + NY * NZ), __ldg(p + NY * NZ + NZ),
                       fx, fy, fz);
}

__device__ __forceinline__ void slab_clip(float p0, float dd, float lo, float hi,
                                          float& t0, float& t1) {
    if (fabsf(dd) > 1e-9f) {
        float r = 1.0f / dd;
        float ta = (lo - p0) * r, tb = (hi - p0) * r;
        t0 = fmaxf(t0, fminf(ta, tb));
        t1 = fminf(t1, fmaxf(ta, tb));
    } else if (p0 <= lo || p0 >= hi) {
        t1 = -1e9f;
    }
}

// ---------------------------------------------------------------------------
// Kernel B: cone-beam forward projection
// block = (128 v-threads, 2 step-halves) = 256 threads; grid = (u, view)
// Interior loop: 8 samples/iter, 32 loads batched before consumption (MLP)
// ---------------------------------------------------------------------------
__global__ void __launch_bounds__(256, 3)
proj_kernel(const float* __restrict__ src_pos,
            const float* __restrict__ det_center,
            const float* __restrict__ det_u_vec,
            const float* __restrict__ det_v_vec,
            const float* __restrict__ pdu,
            const float* __restrict__ pdv,
            const float* __restrict__ psp,
            float* __restrict__ sino) {
    const int v = threadIdx.x;
    const int ty = threadIdx.y;     // step-range half (0..1)
    const int u = blockIdx.x;
    const int view = blockIdx.y;

    const float du = __ldg(pdu);
    const float dv = __ldg(pdv);
    const float inv_sp = 1.0f / __ldg(psp);

    const float sx = __ldg(&src_pos[view * 3 + 0]);
    const float sy = __ldg(&src_pos[view * 3 + 1]);
    const float sz = __ldg(&src_pos[view * 3 + 2]);
    const float ccx = __ldg(&det_center[view * 3 + 0]);
    const float ccy = __ldg(&det_center[view * 3 + 1]);
    const float ccz = __ldg(&det_center[view * 3 + 2]);
    const float ux = __ldg(&det_u_vec[view * 3 + 0]);
    const float uy = __ldg(&det_u_vec[view * 3 + 1]);
    const float uz = __ldg(&det_u_vec[view * 3 + 2]);
    const float vx = __ldg(&det_v_vec[view * 3 + 0]);
    const float vy = __ldg(&det_v_vec[view * 3 + 1]);
    const float vz = __ldg(&det_v_vec[view * 3 + 2]);

    const float uu = ((float)u - (float)(DETU - 1) * 0.5f) * du;
    const float vv = ((float)v - (float)(DETV - 1) * 0.5f) * dv;

    const float dx = (ccx + uu * ux + vv * vx) - sx;
    const float dy = (ccy + uu * uy + vv * vy) - sy;
    const float dz = (ccz + uu * uz + vv * vz) - sz;
    const float ray_len = sqrtf(dx * dx + dy * dy + dz * dz);

    const float cx = (float)(NX - 1) * 0.5f;
    const float cy = (float)(NY - 1) * 0.5f;
    const float cz = (float)(NZ - 1) * 0.5f;
    const float p0x = fmaf(sx, inv_sp, cx);
    const float p0y = fmaf(sy, inv_sp, cy);
    const float p0z = fmaf(sz, inv_sp, cz);
    const float ddx = dx * inv_sp;
    const float ddy = dy * inv_sp;
    const float ddz = dz * inv_sp;

    // outer clip
    float t0 = 0.0f, t1 = 1.0f;
    slab_clip(p0x, ddx, -1.0f, (float)NX, t0, t1);
    slab_clip(p0y, ddy, -1.0f, (float)NY, t0, t1);
    slab_clip(p0z, ddz, -1.0f, (float)NZ, t0, t1);

    int k0 = 0, k1 = -1;
    if (t1 > t0) {
        k0 = max((int)ceilf(t0 * (float)NSTEPS - 0.5f) - 1, 0);
        k1 = min((int)floorf(t1 * (float)NSTEPS - 0.5f) + 1, NSTEPS - 1);
    }

    // interior clip
    float s0 = 0.0f, s1 = 1.0f;
    slab_clip(p0x, ddx, 1e-3f, (float)NX - 1.001f, s0, s1);
    slab_clip(p0y, ddy, 1e-3f, (float)NY - 1.001f, s0, s1);
    slab_clip(p0z, ddz, 1e-3f, (float)NZ - 1.001f, s0, s1);

    int ki0, ki1;
    if (s1 > s0) {
        ki0 = max((int)ceilf(s0 * (float)NSTEPS - 0.5f) + 1, k0);
        ki1 = min((int)floorf(s1 * (float)NSTEPS - 0.5f) - 1, k1);
    } else {
        ki0 = k1 + 1; ki1 = k1;
    }
    if (ki1 < ki0) { ki0 = k1 + 1; ki1 = k1; }

    const float inv_n = 1.0f / (float)NSTEPS;
    const float ddnx = ddx * inv_n, ddny = ddy * inv_n, ddnz = ddz * inv_n;
    const float bx = fmaf(0.5f, ddnx, p0x);
    const float by = fmaf(0.5f, ddny, p0y);
    const float bz = fmaf(0.5f, ddnz, p0z);

    // split step range into halves across the two y-threads
    const int n = max(k1 - k0 + 1, 0);
    const int a = k0 + (n * ty) / 2;
    const int b = k0 + (n * (ty + 1)) / 2 - 1;

    float acc = 0.0f;

    // leading boundary (masked)
    for (int k = a; k <= min(b, ki0 - 1); ++k) {
        float kf = (float)k;
        acc += trilin_masked(fmaf(kf, ddnx, bx), fmaf(kf, ddny, by), fmaf(kf, ddnz, bz));
    }

    // interior: 8 samples per iteration, 32 loads batched
    int kk = max(a, ki0);
    const int kend = min(b, ki1);

#define PREP(i, KF)                                                           \
    float px##i = fmaf((KF), ddnx, bx);                                       \
    float py##i = fmaf((KF), ddny, by);                                       \
    float pz##i = fmaf((KF), ddnz, bz);                                       \
    float xf##i = floorf(px##i), yf##i = floorf(py##i), zf##i = floorf(pz##i);\
    float fx##i = px##i - xf##i, fy##i = py##i - yf##i, fz##i = pz##i - zf##i;\
    const __half2* q##i = g_pair +                                            \
        (((int)xf##i * NY + (int)yf##i) * NZ + (int)zf##i);

#define LOADS(i)                                                              \
    __half2 A##i = __ldg(q##i);                                               \
    __half2 B##i = __ldg(q##i + NZ);                                          \
    __half2 C##i = __ldg(q##i + NY * NZ);                                     \
    __half2 D##i = __ldg(q##i + NY * NZ + NZ);

    for (; kk + 7 <= kend; kk += 8) {
        PREP(0, (float)kk)
        PREP(1, (float)(kk + 1))
        PREP(2, (float)(kk + 2))
        PREP(3, (float)(kk + 3))
        PREP(4, (float)(kk + 4))
        PREP(5, (float)(kk + 5))
        PREP(6, (float)(kk + 6))
        PREP(7, (float)(kk + 7))

        LOADS(0) LOADS(1) LOADS(2) LOADS(3)
        LOADS(4) LOADS(5) LOADS(6) LOADS(7)

        acc += tri_combine(A0, B0, C0, D0, fx0, fy0, fz0);
        acc += tri_combine(A1, B1, C1, D1, fx1, fy1, fz1);
        acc += tri_combine(A2, B2, C2, D2, fx2, fy2, fz2);
        acc += tri_combine(A3, B3, C3, D3, fx3, fy3, fz3);
        acc += tri_combine(A4, B4, C4, D4, fx4, fy4, fz4);
        acc += tri_combine(A5, B5, C5, D5, fx5, fy5, fz5);
        acc += tri_combine(A6, B6, C6, D6, fx6, fy6, fz6);
        acc += tri_combine(A7, B7, C7, D7, fx7, fy7, fz7);
    }
    for (; kk + 3 <= kend; kk += 4) {
        PREP(0, (float)kk)
        PREP(1, (float)(kk + 1))
        PREP(2, (float)(kk + 2))
        PREP(3, (float)(kk + 3))
        LOADS(0) LOADS(1) LOADS(2) LOADS(3)
        acc += tri_combine(A0, B0, C0, D0, fx0, fy0, fz0);
        acc += tri_combine(A1, B1, C1, D1, fx1, fy1, fz1);
        acc += tri_combine(A2, B2, C2, D2, fx2, fy2, fz2);
        acc += tri_combine(A3, B3, C3, D3, fx3, fy3, fz3);
    }
    for (; kk <= kend; ++kk) {
        float kf = (float)kk;
        acc += trilin_fast(fmaf(kf, ddnx, bx), fmaf(kf, ddny, by), fmaf(kf, ddnz, bz));
    }
#undef PREP
#undef LOADS

    // trailing boundary (masked)
    for (int k = max(a, ki1 + 1); k <= b; ++k) {
        float kf = (float)k;
        acc += trilin_masked(fmaf(kf, ddnx, bx), fmaf(kf, ddny, by), fmaf(kf, ddnz, bz));
    }

    __shared__ float part[DETV];
    if (ty == 1) part[v] = acc;
    __syncthreads();
    if (ty == 0) {
        sino[(view * DETU + u) * DETV + v] = (acc + part[v]) * (ray_len * inv_n);
    }
}

// ---------------------------------------------------------------------------
// Launch
// ---------------------------------------------------------------------------
extern "C" void kernel_launch(void* const* d_in, const int* in_sizes, int n_in,
                              void* d_out, int out_size) {
    const float* x    = (const float*)d_in[0];
    const float* reco = (const float*)d_in[1];
    const float* src  = (const float*)d_in[2];
    const float* dc   = (const float*)d_in[3];
    const float* duv  = (const float*)d_in[4];
    const float* dvv  = (const float*)d_in[5];
    const float* pdu  = (const float*)d_in[6];
    const float* pdv  = (const float*)d_in[7];
    const float* psp  = (const float*)d_in[8];

    float* out  = (float*)d_out;
    float* sino = out;                                   // [8,128,128]
    float* relu = out + NVIEWS * DETU * DETV;            // [256^3]

    const int n4 = (NX * NY * NZ) / 4;
    add_relu_pack_kernel<<<n4 / 256, 256>>>(x, reco, relu);

    dim3 grid(DETU, NVIEWS);
    dim3 block(DETV, 2);
    proj_kernel<<<grid, block>>>(src, dc, duv, dvv, pdu, pdv, psp, sino);
}

// round 8
// speedup vs baseline: 1.0435x; 1.0435x over previous
#include <cuda_runtime.h>
#include <cuda_fp16.h>

#define NX 256
#define NY 256
#define NZ 256
#define DETU 128
#define DETV 128
#define NVIEWS 8
#define NSTEPS 192

// Padded packed volume dims: voxel (x,y,z), x0 in [-1,257] -> xi = x0+1 in [0,258]
#define PXD 259
#define PYD 259
#define PZD 260   // z-stride padded to multiple of 4 for aligned uint4 row stores

// g_pairP[(xi*PYD + yi)*PZD + zi] = ( half(v[zi-1]), half(v[zi]) ), zeros in pads
__device__ __half2 g_pairP[PXD * PYD * PZD];   // ~69.8 MB

// ---------------------------------------------------------------------------
// Kernel A0: zero the pad borders (x-planes {0,257,258}, y-planes {0,257,258})
// z pads are written by the pack kernel's row fill.
// ---------------------------------------------------------------------------
__global__ void zero_border_kernel() {
    int idx = blockIdx.x * blockDim.x + threadIdx.x;
    const int planeA = 3 * PYD * PZD;        // xi in {0,257,258}, all (yi,zi)
    const int planeB = 3 * 256 * PZD;        // yi in {0,257,258}, xi in 1..256
    __half2 zero = __floats2half2_rn(0.0f, 0.0f);
    if (idx < planeA) {
        int p = idx / (PYD * PZD);
        int rem = idx - p * (PYD * PZD);
        int xi = (p == 0) ? 0 : (p == 1 ? 257 : 258);
        g_pairP[xi * (PYD * PZD) + rem] = zero;
    } else if (idx < planeA + planeB) {
        int j = idx - planeA;
        int p = j / (256 * PZD);
        int rem = j - p * (256 * PZD);
        int yi = (p == 0) ? 0 : (p == 1 ? 257 : 258);
        int xi = 1 + rem / PZD;
        int zi = rem - (rem / PZD) * PZD;
        g_pairP[(xi * PYD + yi) * PZD + zi] = zero;
    }
}

// ---------------------------------------------------------------------------
// Kernel A (fused): relu_out = max(x+reco,0) ; padded z-pair volume fill
// Each thread handles 4 z-values of one (x,y) row; writes pairs zi=4t..4t+3:
//   pair[zi] = ( v[zi-1], v[zi] )   (v[-1]=0 handled via t==0)
// Thread t==63 also writes zi=256..259 tail (v[255],0),(0,0),(0,0),(0,0).
// ---------------------------------------------------------------------------
__global__ void add_relu_pack_kernel(const float* __restrict__ x,
                                     const float* __restrict__ r,
                                     float* __restrict__ relu_out) {
    int i = blockIdx.x * blockDim.x + threadIdx.x;   // float4 index, 256^3/4 total
    const float4* x4 = (const float4*)x;
    const float4* r4 = (const float4*)r;
    float4 a = x4[i];
    float4 b = r4[i];
    float4 s;
    s.x = a.x + b.x; s.y = a.y + b.y; s.z = a.z + b.z; s.w = a.w + b.w;

    float4 rl;
    rl.x = fmaxf(s.x, 0.0f); rl.y = fmaxf(s.y, 0.0f);
    rl.z = fmaxf(s.z, 0.0f); rl.w = fmaxf(s.w, 0.0f);
    ((float4*)relu_out)[i] = rl;

    int base = i * 4;
    int t = i & 63;              // z-chunk index within row (z = 4t)
    int row = i >> 6;            // x*256 + y
    int xi = (row >> 8) + 1;
    int yi = (row & 255) + 1;

    float prev = 0.0f;
    if (t > 0) prev = x[base - 1] + r[base - 1];

    __half2* rowp = g_pairP + (xi * PYD + yi) * PZD;

    union { __half2 h[4]; uint4 u; } pk;
    pk.h[0] = __floats2half2_rn(prev, s.x);
    pk.h[1] = __floats2half2_rn(s.x, s.y);
    pk.h[2] = __floats2half2_rn(s.y, s.z);
    pk.h[3] = __floats2half2_rn(s.z, s.w);
    ((uint4*)rowp)[t] = pk.u;

    if (t == 63) {
        union { __half2 h[4]; uint4 u; } pk2;
        pk2.h[0] = __floats2half2_rn(s.w, 0.0f);
        pk2.h[1] = __floats2half2_rn(0.0f, 0.0f);
        pk2.h[2] = pk2.h[1];
        pk2.h[3] = pk2.h[1];
        ((uint4*)rowp)[64] = pk2.u;
    }
}

// ---------------------------------------------------------------------------
// combine 4 packed corner loads with weights
// ---------------------------------------------------------------------------
__device__ __forceinline__ float tri_combine(__half2 A, __half2 B, __half2 C, __half2 D,
                                             float fx, float fy, float fz) {
    float2 a = __half22float2(A);
    float2 b = __half22float2(B);
    float2 c = __half22float2(C);
    float2 d = __half22float2(D);
    float gz = 1.0f - fz, gy = 1.0f - fy, gx = 1.0f - fx;
    float c00 = a.x * gz + a.y * fz;
    float c01 = b.x * gz + b.y * fz;
    float c10 = c.x * gz + c.y * fz;
    float c11 = d.x * gz + d.y * fz;
    float c0 = c00 * gy + c01 * fy;
    float c1 = c10 * gy + c11 * fy;
    return c0 * gx + c1 * fx;
}

// Single sample (tail); clamp to [-1,256] makes out-of-range exactly 0 via pads
__device__ __forceinline__ float trilin_pad(float px, float py, float pz) {
    px = fminf(fmaxf(px, -1.0f), 256.0f);
    py = fminf(fmaxf(py, -1.0f), 256.0f);
    pz = fminf(fmaxf(pz, -1.0f), 256.0f);
    float xf = floorf(px), yf = floorf(py), zf = floorf(pz);
    float fx = px - xf, fy = py - yf, fz = pz - zf;
    int xi = (int)xf + 1, yi = (int)yf + 1, zi = (int)zf + 1;
    const __half2* q = g_pairP + ((xi * PYD + yi) * PZD + zi);
    return tri_combine(__ldg(q), __ldg(q + PZD),
                       __ldg(q + PYD * PZD), __ldg(q + PYD * PZD + PZD),
                       fx, fy, fz);
}

__device__ __forceinline__ void slab_clip(float p0, float dd, float lo, float hi,
                                          float& t0, float& t1) {
    if (fabsf(dd) > 1e-9f) {
        float r = 1.0f / dd;
        float ta = (lo - p0) * r, tb = (hi - p0) * r;
        t0 = fmaxf(t0, fminf(ta, tb));
        t1 = fminf(t1, fmaxf(ta, tb));
    } else if (p0 <= lo || p0 >= hi) {
        t1 = -1e9f;
    }
}

// ---------------------------------------------------------------------------
// Kernel B: cone-beam forward projection — uniform padded fast path
// block = (128 v-threads, 2 step-halves); grid = (u, view)
// ---------------------------------------------------------------------------
__global__ void __launch_bounds__(256, 4)
proj_kernel(const float* __restrict__ src_pos,
            const float* __restrict__ det_center,
            const float* __restrict__ det_u_vec,
            const float* __restrict__ det_v_vec,
            const float* __restrict__ pdu,
            const float* __restrict__ pdv,
            const float* __restrict__ psp,
            float* __restrict__ sino) {
    const int v = threadIdx.x;
    const int ty = threadIdx.y;     // step-range half (0..1)
    const int u = blockIdx.x;
    const int view = blockIdx.y;

    const float du = __ldg(pdu);
    const float dv = __ldg(pdv);
    const float inv_sp = 1.0f / __ldg(psp);

    const float sx = __ldg(&src_pos[view * 3 + 0]);
    const float sy = __ldg(&src_pos[view * 3 + 1]);
    const float sz = __ldg(&src_pos[view * 3 + 2]);
    const float ccx = __ldg(&det_center[view * 3 + 0]);
    const float ccy = __ldg(&det_center[view * 3 + 1]);
    const float ccz = __ldg(&det_center[view * 3 + 2]);
    const float ux = __ldg(&det_u_vec[view * 3 + 0]);
    const float uy = __ldg(&det_u_vec[view * 3 + 1]);
    const float uz = __ldg(&det_u_vec[view * 3 + 2]);
    const float vx = __ldg(&det_v_vec[view * 3 + 0]);
    const float vy = __ldg(&det_v_vec[view * 3 + 1]);
    const float vz = __ldg(&det_v_vec[view * 3 + 2]);

    const float uu = ((float)u - (float)(DETU - 1) * 0.5f) * du;
    const float vv = ((float)v - (float)(DETV - 1) * 0.5f) * dv;

    const float dx = (ccx + uu * ux + vv * vx) - sx;
    const float dy = (ccy + uu * uy + vv * vy) - sy;
    const float dz = (ccz + uu * uz + vv * vz) - sz;
    const float ray_len = sqrtf(dx * dx + dy * dy + dz * dz);

    const float cx = (float)(NX - 1) * 0.5f;
    const float cy = (float)(NY - 1) * 0.5f;
    const float cz = (float)(NZ - 1) * 0.5f;
    const float p0x = fmaf(sx, inv_sp, cx);
    const float p0y = fmaf(sy, inv_sp, cy);
    const float p0z = fmaf(sz, inv_sp, cz);
    const float ddx = dx * inv_sp;
    const float ddy = dy * inv_sp;
    const float ddz = dz * inv_sp;

    // outer clip: beyond (-1, N) in any dim contributes exactly 0 (zero pads)
    float t0 = 0.0f, t1 = 1.0f;
    slab_clip(p0x, ddx, -1.0f, (float)NX, t0, t1);
    slab_clip(p0y, ddy, -1.0f, (float)NY, t0, t1);
    slab_clip(p0z, ddz, -1.0f, (float)NZ, t0, t1);

    int k0 = 0, k1 = -1;
    if (t1 > t0) {
        k0 = max((int)ceilf(t0 * (float)NSTEPS - 0.5f) - 1, 0);
        k1 = min((int)floorf(t1 * (float)NSTEPS - 0.5f) + 1, NSTEPS - 1);
    }

    const float inv_n = 1.0f / (float)NSTEPS;
    const float ddnx = ddx * inv_n, ddny = ddy * inv_n, ddnz = ddz * inv_n;
    const float bx = fmaf(0.5f, ddnx, p0x);
    const float by = fmaf(0.5f, ddny, p0y);
    const float bz = fmaf(0.5f, ddnz, p0z);

    // split step range into halves across the two y-threads
    const int n = max(k1 - k0 + 1, 0);
    const int a = k0 + (n * ty) / 2;
    const int b = k0 + (n * (ty + 1)) / 2 - 1;

    float acc = 0.0f;
    int kk = a;

#define PREP(i, KF)                                                            \
    float px##i = fminf(fmaxf(fmaf((KF), ddnx, bx), -1.0f), 256.0f);           \
    float py##i = fminf(fmaxf(fmaf((KF), ddny, by), -1.0f), 256.0f);           \
    float pz##i = fminf(fmaxf(fmaf((KF), ddnz, bz), -1.0f), 256.0f);           \
    float xf##i = floorf(px##i), yf##i = floorf(py##i), zf##i = floorf(pz##i); \
    float fx##i = px##i - xf##i, fy##i = py##i - yf##i, fz##i = pz##i - zf##i; \
    const __half2* q##i = g_pairP +                                            \
        ((((int)xf##i + 1) * PYD + ((int)yf##i + 1)) * PZD + ((int)zf##i + 1));

#define LOADS(i)                                                               \
    __half2 A##i = __ldg(q##i);                                                \
    __half2 B##i = __ldg(q##i + PZD);                                          \
    __half2 C##i = __ldg(q##i + PYD * PZD);                                    \
    __half2 D##i = __ldg(q##i + PYD * PZD + PZD);

    // 4 samples per iteration, 16 loads batched before consumption (MLP)
    for (; kk + 3 <= b; kk += 4) {
        PREP(0, (float)kk)
        PREP(1, (float)(kk + 1))
        PREP(2, (float)(kk + 2))
        PREP(3, (float)(kk + 3))

        LOADS(0) LOADS(1) LOADS(2) LOADS(3)

        acc += tri_combine(A0, B0, C0, D0, fx0, fy0, fz0);
        acc += tri_combine(A1, B1, C1, D1, fx1, fy1, fz1);
        acc += tri_combine(A2, B2, C2, D2, fx2, fy2, fz2);
        acc += tri_combine(A3, B3, C3, D3, fx3, fy3, fz3);
    }
    for (; kk <= b; ++kk) {
        float kf = (float)kk;
        acc += trilin_pad(fmaf(kf, ddnx, bx), fmaf(kf, ddny, by), fmaf(kf, ddnz, bz));
    }
#undef PREP
#undef LOADS

    __shared__ float part[DETV];
    if (ty == 1) part[v] = acc;
    __syncthreads();
    if (ty == 0) {
        sino[(view * DETU + u) * DETV + v] = (acc + part[v]) * (ray_len * inv_n);
    }
}

// ---------------------------------------------------------------------------
// Launch
// ---------------------------------------------------------------------------
extern "C" void kernel_launch(void* const* d_in, const int* in_sizes, int n_in,
                              void* d_out, int out_size) {
    const float* x    = (const float*)d_in[0];
    const float* reco = (const float*)d_in[1];
    const float* src  = (const float*)d_in[2];
    const float* dc   = (const float*)d_in[3];
    const float* duv  = (const float*)d_in[4];
    const float* dvv  = (const float*)d_in[5];
    const float* pdu  = (const float*)d_in[6];
    const float* pdv  = (const float*)d_in[7];
    const float* psp  = (const float*)d_in[8];

    float* out  = (float*)d_out;
    float* sino = out;                                   // [8,128,128]
    float* relu = out + NVIEWS * DETU * DETV;            // [256^3]

    // zero pad borders (disjoint from pack kernel's rows; both precede proj)
    const int nborder = 3 * PYD * PZD + 3 * 256 * PZD;
    zero_border_kernel<<<(nborder + 255) / 256, 256>>>();

    const int n4 = (NX * NY * NZ) / 4;
    add_relu_pack_kernel<<<n4 / 256, 256>>>(x, reco, relu);

    dim3 grid(DETU, NVIEWS);
    dim3 block(DETV, 2);
    proj_kernel<<<grid, block>>>(src, dc, duv, dvv, pdu, pdv, psp, sino);
}

// round 9
// speedup vs baseline: 1.0599x; 1.0157x over previous
#include <cuda_runtime.h>
#include <cuda_fp16.h>

#define NX 256
#define NY 256
#define NZ 256
#define DETU 128
#define DETV 128
#define NVIEWS 8
#define NSTEPS 192

// Padded packed volume dims: voxel (x,y,z), x0 in [-1,257] -> xi = x0+1 in [0,258]
#define PXD 259
#define PYD 259
#define PZD 260   // z-stride padded to multiple of 4 for aligned uint4 row stores

// g_pairP[(xi*PYD + yi)*PZD + zi] = ( half(v[zi-1]), half(v[zi]) ), zeros in pads
__device__ __half2 g_pairP[PXD * PYD * PZD];   // ~69.8 MB

#define MAIN_BLOCKS ((NX * NY * NZ / 4) / 256)          // 16384
#define NBORDER (3 * PYD * PZD + 3 * 256 * PZD)         // border half2 count
#define BORDER_BLOCKS ((NBORDER + 255) / 256)           // 1570

// ---------------------------------------------------------------------------
// Kernel A (fused): relu_out = max(x+reco,0) ; padded z-pair volume fill ;
// border zeroing folded into trailing blocks (rides along with HBM-bound work).
// ---------------------------------------------------------------------------
__global__ void add_relu_pack_kernel(const float* __restrict__ x,
                                     const float* __restrict__ r,
                                     float* __restrict__ relu_out) {
    if (blockIdx.x >= MAIN_BLOCKS) {
        // border-zero path: x-planes {0,257,258} all (yi,zi); y-planes {0,257,258} xi 1..256
        int idx = (blockIdx.x - MAIN_BLOCKS) * blockDim.x + threadIdx.x;
        const int planeA = 3 * PYD * PZD;
        __half2 zero = __floats2half2_rn(0.0f, 0.0f);
        if (idx < planeA) {
            int p = idx / (PYD * PZD);
            int rem = idx - p * (PYD * PZD);
            int xi = (p == 0) ? 0 : (p == 1 ? 257 : 258);
            g_pairP[xi * (PYD * PZD) + rem] = zero;
        } else if (idx < NBORDER) {
            int j = idx - planeA;
            int p = j / (256 * PZD);
            int rem = j - p * (256 * PZD);
            int yi = (p == 0) ? 0 : (p == 1 ? 257 : 258);
            int xi = 1 + rem / PZD;
            int zi = rem - (rem / PZD) * PZD;
            g_pairP[(xi * PYD + yi) * PZD + zi] = zero;
        }
        return;
    }

    int i = blockIdx.x * blockDim.x + threadIdx.x;   // float4 index, 256^3/4 total
    const float4* x4 = (const float4*)x;
    const float4* r4 = (const float4*)r;
    float4 a = x4[i];
    float4 b = r4[i];
    float4 s;
    s.x = a.x + b.x; s.y = a.y + b.y; s.z = a.z + b.z; s.w = a.w + b.w;

    float4 rl;
    rl.x = fmaxf(s.x, 0.0f); rl.y = fmaxf(s.y, 0.0f);
    rl.z = fmaxf(s.z, 0.0f); rl.w = fmaxf(s.w, 0.0f);
    // streaming store: relu output is never re-read; keep L2 for g_pairP
    __stcs((float4*)relu_out + i, rl);

    int base = i * 4;
    int t = i & 63;              // z-chunk index within row (z = 4t)
    int row = i >> 6;            // x*256 + y
    int xi = (row >> 8) + 1;
    int yi = (row & 255) + 1;

    float prev = 0.0f;
    if (t > 0) prev = x[base - 1] + r[base - 1];

    __half2* rowp = g_pairP + (xi * PYD + yi) * PZD;

    union { __half2 h[4]; uint4 u; } pk;
    pk.h[0] = __floats2half2_rn(prev, s.x);
    pk.h[1] = __floats2half2_rn(s.x, s.y);
    pk.h[2] = __floats2half2_rn(s.y, s.z);
    pk.h[3] = __floats2half2_rn(s.z, s.w);
    ((uint4*)rowp)[t] = pk.u;

    if (t == 63) {
        union { __half2 h[4]; uint4 u; } pk2;
        pk2.h[0] = __floats2half2_rn(s.w, 0.0f);
        pk2.h[1] = __floats2half2_rn(0.0f, 0.0f);
        pk2.h[2] = pk2.h[1];
        pk2.h[3] = pk2.h[1];
        ((uint4*)rowp)[64] = pk2.u;
    }
}

// ---------------------------------------------------------------------------
// combine 4 packed corner loads with weights
// ---------------------------------------------------------------------------
__device__ __forceinline__ float tri_combine(__half2 A, __half2 B, __half2 C, __half2 D,
                                             float fx, float fy, float fz) {
    float2 a = __half22float2(A);
    float2 b = __half22float2(B);
    float2 c = __half22float2(C);
    float2 d = __half22float2(D);
    float gz = 1.0f - fz, gy = 1.0f - fy, gx = 1.0f - fx;
    float c00 = a.x * gz + a.y * fz;
    float c01 = b.x * gz + b.y * fz;
    float c10 = c.x * gz + c.y * fz;
    float c11 = d.x * gz + d.y * fz;
    float c0 = c00 * gy + c01 * fy;
    float c1 = c10 * gy + c11 * fy;
    return c0 * gx + c1 * fx;
}

// Single sample (tail); clamp to [-1,256] makes out-of-range exactly 0 via pads
__device__ __forceinline__ float trilin_pad(float px, float py, float pz) {
    px = fminf(fmaxf(px, -1.0f), 256.0f);
    py = fminf(fmaxf(py, -1.0f), 256.0f);
    pz = fminf(fmaxf(pz, -1.0f), 256.0f);
    float xf = floorf(px), yf = floorf(py), zf = floorf(pz);
    float fx = px - xf, fy = py - yf, fz = pz - zf;
    int xi = (int)xf + 1, yi = (int)yf + 1, zi = (int)zf + 1;
    const __half2* q = g_pairP + ((xi * PYD + yi) * PZD + zi);
    return tri_combine(__ldg(q), __ldg(q + PZD),
                       __ldg(q + PYD * PZD), __ldg(q + PYD * PZD + PZD),
                       fx, fy, fz);
}

__device__ __forceinline__ void slab_clip(float p0, float dd, float lo, float hi,
                                          float& t0, float& t1) {
    if (fabsf(dd) > 1e-9f) {
        float r = 1.0f / dd;
        float ta = (lo - p0) * r, tb = (hi - p0) * r;
        t0 = fmaxf(t0, fminf(ta, tb));
        t1 = fminf(t1, fmaxf(ta, tb));
    } else if (p0 <= lo || p0 >= hi) {
        t1 = -1e9f;
    }
}

// ---------------------------------------------------------------------------
// Kernel B: cone-beam forward projection — uniform padded fast path
// block = (128 v-threads, 2 step-halves); grid = (u, view)
// ---------------------------------------------------------------------------
__global__ void __launch_bounds__(256, 4)
proj_kernel(const float* __restrict__ src_pos,
            const float* __restrict__ det_center,
            const float* __restrict__ det_u_vec,
            const float* __restrict__ det_v_vec,
            const float* __restrict__ pdu,
            const float* __restrict__ pdv,
            const float* __restrict__ psp,
            float* __restrict__ sino) {
    const int v = threadIdx.x;
    const int ty = threadIdx.y;     // step-range half (0..1)
    const int u = blockIdx.x;
    const int view = blockIdx.y;

    const float du = __ldg(pdu);
    const float dv = __ldg(pdv);
    const float inv_sp = 1.0f / __ldg(psp);

    const float sx = __ldg(&src_pos[view * 3 + 0]);
    const float sy = __ldg(&src_pos[view * 3 + 1]);
    const float sz = __ldg(&src_pos[view * 3 + 2]);
    const float ccx = __ldg(&det_center[view * 3 + 0]);
    const float ccy = __ldg(&det_center[view * 3 + 1]);
    const float ccz = __ldg(&det_center[view * 3 + 2]);
    const float ux = __ldg(&det_u_vec[view * 3 + 0]);
    const float uy = __ldg(&det_u_vec[view * 3 + 1]);
    const float uz = __ldg(&det_u_vec[view * 3 + 2]);
    const float vx = __ldg(&det_v_vec[view * 3 + 0]);
    const float vy = __ldg(&det_v_vec[view * 3 + 1]);
    const float vz = __ldg(&det_v_vec[view * 3 + 2]);

    const float uu = ((float)u - (float)(DETU - 1) * 0.5f) * du;
    const float vv = ((float)v - (float)(DETV - 1) * 0.5f) * dv;

    const float dx = (ccx + uu * ux + vv * vx) - sx;
    const float dy = (ccy + uu * uy + vv * vy) - sy;
    const float dz = (ccz + uu * uz + vv * vz) - sz;
    const float ray_len = sqrtf(dx * dx + dy * dy + dz * dz);

    const float cx = (float)(NX - 1) * 0.5f;
    const float cy = (float)(NY - 1) * 0.5f;
    const float cz = (float)(NZ - 1) * 0.5f;
    const float p0x = fmaf(sx, inv_sp, cx);
    const float p0y = fmaf(sy, inv_sp, cy);
    const float p0z = fmaf(sz, inv_sp, cz);
    const float ddx = dx * inv_sp;
    const float ddy = dy * inv_sp;
    const float ddz = dz * inv_sp;

    // outer clip: beyond (-1, N) in any dim contributes exactly 0 (zero pads)
    float t0 = 0.0f, t1 = 1.0f;
    slab_clip(p0x, ddx, -1.0f, (float)NX, t0, t1);
    slab_clip(p0y, ddy, -1.0f, (float)NY, t0, t1);
    slab_clip(p0z, ddz, -1.0f, (float)NZ, t0, t1);

    int k0 = 0, k1 = -1;
    if (t1 > t0) {
        k0 = max((int)ceilf(t0 * (float)NSTEPS - 0.5f) - 1, 0);
        k1 = min((int)floorf(t1 * (float)NSTEPS - 0.5f) + 1, NSTEPS - 1);
    }

    const float inv_n = 1.0f / (float)NSTEPS;
    const float ddnx = ddx * inv_n, ddny = ddy * inv_n, ddnz = ddz * inv_n;
    const float bx = fmaf(0.5f, ddnx, p0x);
    const float by = fmaf(0.5f, ddny, p0y);
    const float bz = fmaf(0.5f, ddnz, p0z);

    // split step range into halves across the two y-threads
    const int n = max(k1 - k0 + 1, 0);
    const int a = k0 + (n * ty) / 2;
    const int b = k0 + (n * (ty + 1)) / 2 - 1;

    float acc = 0.0f;
    int kk = a;

#define PREP(i, KF)                                                            \
    float px##i = fminf(fmaxf(fmaf((KF), ddnx, bx), -1.0f), 256.0f);           \
    float py##i = fminf(fmaxf(fmaf((KF), ddny, by), -1.0f), 256.0f);           \
    float pz##i = fminf(fmaxf(fmaf((KF), ddnz, bz), -1.0f), 256.0f);           \
    float xf##i = floorf(px##i), yf##i = floorf(py##i), zf##i = floorf(pz##i); \
    float fx##i = px##i - xf##i, fy##i = py##i - yf##i, fz##i = pz##i - zf##i; \
    const __half2* q##i = g_pairP +                                            \
        ((((int)xf##i + 1) * PYD + ((int)yf##i + 1)) * PZD + ((int)zf##i + 1));

#define LOADS(i)                                                               \
    __half2 A##i = __ldg(q##i);                                                \
    __half2 B##i = __ldg(q##i + PZD);                                          \
    __half2 C##i = __ldg(q##i + PYD * PZD);                                    \
    __half2 D##i = __ldg(q##i + PYD * PZD + PZD);

    // 4 samples per iteration, 16 loads batched before consumption (MLP)
    for (; kk + 3 <= b; kk += 4) {
        PREP(0, (float)kk)
        PREP(1, (float)(kk + 1))
        PREP(2, (float)(kk + 2))
        PREP(3, (float)(kk + 3))

        LOADS(0) LOADS(1) LOADS(2) LOADS(3)

        acc += tri_combine(A0, B0, C0, D0, fx0, fy0, fz0);
        acc += tri_combine(A1, B1, C1, D1, fx1, fy1, fz1);
        acc += tri_combine(A2, B2, C2, D2, fx2, fy2, fz2);
        acc += tri_combine(A3, B3, C3, D3, fx3, fy3, fz3);
    }
    for (; kk <= b; ++kk) {
        float kf = (float)kk;
        acc += trilin_pad(fmaf(kf, ddnx, bx), fmaf(kf, ddny, by), fmaf(kf, ddnz, bz));
    }
#undef PREP
#undef LOADS

    __shared__ float part[DETV];
    if (ty == 1) part[v] = acc;
    __syncthreads();
    if (ty == 0) {
        sino[(view * DETU + u) * DETV + v] = (acc + part[v]) * (ray_len * inv_n);
    }
}

// ---------------------------------------------------------------------------
// Launch
// ---------------------------------------------------------------------------
extern "C" void kernel_launch(void* const* d_in, const int* in_sizes, int n_in,
                              void* d_out, int out_size) {
    const float* x    = (const float*)d_in[0];
    const float* reco = (const float*)d_in[1];
    const float* src  = (const float*)d_in[2];
    const float* dc   = (const float*)d_in[3];
    const float* duv  = (const float*)d_in[4];
    const float* dvv  = (const float*)d_in[5];
    const float* pdu  = (const float*)d_in[6];
    const float* pdv  = (const float*)d_in[7];
    const float* psp  = (const float*)d_in[8];

    float* out  = (float*)d_out;
    float* sino = out;                                   // [8,128,128]
    float* relu = out + NVIEWS * DETU * DETV;            // [256^3]

    // fused: main blocks do add/relu/pack, trailing blocks zero pad borders
    add_relu_pack_kernel<<<MAIN_BLOCKS + BORDER_BLOCKS, 256>>>(x, reco, relu);

    dim3 grid(DETU, NVIEWS);
    dim3 block(DETV, 2);
    proj_kernel<<<grid, block>>>(src, dc, duv, dvv, pdu, pdv, psp, sino);
}